// round 1
// baseline (speedup 1.0000x reference)
#include <cuda_runtime.h>
#include <cuda_bf16.h>
#include <math.h>

// ---------------------------------------------------------------------------
// GraphSAGE (3x SAGEConv mean + ReLU, softmax) on GB300.
// Inputs (metadata order):
//  0 in_feat [N,128] f32, 1 src [E] i32, 2 dst [E] i32,
//  3 w1_self[128,128], 4 w1_neigh[128,128], 5 b1[128],
//  6 w2_self[128,64],  7 w2_neigh[128,64],  8 b2[64],
//  9 w3_self[64,64],  10 w3_neigh[64,64],  11 b3[64]
// Output: [N,64] f32 (softmax rows)
// ---------------------------------------------------------------------------

#define MAXN 100000
#define MAXE 1600000

__device__ int   g_deg[MAXN];
__device__ int   g_rowptr[MAXN + 1];
__device__ int   g_cursor[MAXN];
__device__ int   g_colidx[MAXE];
__device__ float g_invdeg[MAXN];
__device__ float g_agg[(size_t)MAXN * 128];
__device__ float g_h1[(size_t)MAXN * 128];
__device__ float g_h2[(size_t)MAXN * 64];

// ---------------------------- CSR construction ----------------------------

__global__ void zero_int_kernel(int* p, int n) {
    int i = blockIdx.x * blockDim.x + threadIdx.x;
    if (i < n) p[i] = 0;
}

__global__ void count_deg_kernel(const int* __restrict__ dst, int* __restrict__ deg, int E) {
    int e = blockIdx.x * blockDim.x + threadIdx.x;
    if (e < E) atomicAdd(&deg[__ldg(&dst[e])], 1);
}

// single-block exclusive scan over deg (n up to 100k), also fills cursor/invdeg
__global__ void scan_deg_kernel(const int* __restrict__ deg, int* __restrict__ rowptr,
                                int* __restrict__ cursor, float* __restrict__ invdeg, int n) {
    __shared__ int ssum[1024];
    int tid = threadIdx.x;
    int chunk = (n + 1023) / 1024;
    int lo = tid * chunk;
    int hi = lo + chunk; if (hi > n) hi = n;
    if (lo > n) lo = n;

    int sum = 0;
    for (int i = lo; i < hi; ++i) sum += deg[i];
    ssum[tid] = sum;
    __syncthreads();
    // Hillis-Steele inclusive scan
    for (int off = 1; off < 1024; off <<= 1) {
        int v = (tid >= off) ? ssum[tid - off] : 0;
        __syncthreads();
        ssum[tid] += v;
        __syncthreads();
    }
    int run = ssum[tid] - sum;  // exclusive prefix
    for (int i = lo; i < hi; ++i) {
        rowptr[i] = run;
        cursor[i] = run;
        float d = (float)deg[i];
        invdeg[i] = 1.0f / fmaxf(d, 1.0f);
        run += deg[i];
    }
    if (tid == 1023) rowptr[n] = ssum[1023];
}

__global__ void fill_csr_kernel(const int* __restrict__ src, const int* __restrict__ dst,
                                int* __restrict__ cursor, int* __restrict__ colidx, int E) {
    int e = blockIdx.x * blockDim.x + threadIdx.x;
    if (e < E) {
        int d = __ldg(&dst[e]);
        int p = atomicAdd(&cursor[d], 1);
        colidx[p] = __ldg(&src[e]);
    }
}

// ---------------------------- aggregation (mean) ----------------------------
// warp per node; lane covers D/32 contiguous floats. No atomics.

template <int D>
__global__ void aggregate_kernel(const float* __restrict__ X, const int* __restrict__ rowptr,
                                 const int* __restrict__ colidx, const float* __restrict__ invdeg,
                                 float* __restrict__ AG, int n) {
    constexpr int V = D / 32;  // 4 or 2 floats per lane
    int warp = (blockIdx.x * blockDim.x + threadIdx.x) >> 5;
    int lane = threadIdx.x & 31;
    int nwarps = (gridDim.x * blockDim.x) >> 5;

    for (int i = warp; i < n; i += nwarps) {
        int s = __ldg(&rowptr[i]);
        int e = __ldg(&rowptr[i + 1]);
        if (V == 4) {
            float4 acc = make_float4(0.f, 0.f, 0.f, 0.f);
            int j = s;
            for (; j + 1 < e; j += 2) {
                int c0 = __ldg(&colidx[j]);
                int c1 = __ldg(&colidx[j + 1]);
                float4 v0 = __ldg((const float4*)(X + (size_t)c0 * D) + lane);
                float4 v1 = __ldg((const float4*)(X + (size_t)c1 * D) + lane);
                acc.x += v0.x + v1.x; acc.y += v0.y + v1.y;
                acc.z += v0.z + v1.z; acc.w += v0.w + v1.w;
            }
            if (j < e) {
                int c0 = __ldg(&colidx[j]);
                float4 v0 = __ldg((const float4*)(X + (size_t)c0 * D) + lane);
                acc.x += v0.x; acc.y += v0.y; acc.z += v0.z; acc.w += v0.w;
            }
            float inv = __ldg(&invdeg[i]);
            acc.x *= inv; acc.y *= inv; acc.z *= inv; acc.w *= inv;
            ((float4*)(AG + (size_t)i * D))[lane] = acc;
        } else {
            float2 acc = make_float2(0.f, 0.f);
            int j = s;
            for (; j + 1 < e; j += 2) {
                int c0 = __ldg(&colidx[j]);
                int c1 = __ldg(&colidx[j + 1]);
                float2 v0 = __ldg((const float2*)(X + (size_t)c0 * D) + lane);
                float2 v1 = __ldg((const float2*)(X + (size_t)c1 * D) + lane);
                acc.x += v0.x + v1.x; acc.y += v0.y + v1.y;
            }
            if (j < e) {
                int c0 = __ldg(&colidx[j]);
                float2 v0 = __ldg((const float2*)(X + (size_t)c0 * D) + lane);
                acc.x += v0.x; acc.y += v0.y;
            }
            float inv = __ldg(&invdeg[i]);
            acc.x *= inv; acc.y *= inv;
            ((float2*)(AG + (size_t)i * D))[lane] = acc;
        }
    }
}

// ---------------------------- fused SAGE GEMM ----------------------------
// Y[64-row tile] = [X | G] @ [Ws ; Wn] + b, with ReLU (ACT=0) or row-softmax (ACT=1).
// W ([2*K1][OUT]) fully resident in SMEM; A tile [64][2*K1] in SMEM (padded).
// Thread tile: TM rows x 4 cols, float4 smem loads -> FMA-bound.

template <int K1, int OUT, int ACT>
__global__ void gemm_fused(const float* __restrict__ X, const float* __restrict__ G,
                           const float* __restrict__ Ws, const float* __restrict__ Wn,
                           const float* __restrict__ bias, float* __restrict__ Y, int n) {
    constexpr int KC  = 2 * K1;
    constexpr int KCP = KC + 4;      // padded A row stride (still 16B aligned)
    constexpr int CPG = OUT / 4;     // float4 col-chunks per row
    constexpr int RG  = 256 / CPG;   // row lanes
    constexpr int TM  = 64 / RG;     // rows per thread

    extern __shared__ float sm[];
    float* sW = sm;                  // [KC][OUT]
    float* sA = sm + KC * OUT;       // [64][KCP]

    int tid = threadIdx.x;

    // load both weight halves once
    for (int idx = tid * 4; idx < K1 * OUT; idx += 256 * 4) {
        *(float4*)&sW[idx]            = *(const float4*)&Ws[idx];
        *(float4*)&sW[K1 * OUT + idx] = *(const float4*)&Wn[idx];
    }

    int cc = tid % CPG;
    int rg = tid / CPG;
    float4 b4 = __ldg((const float4*)bias + cc);

    int ntiles = (n + 63) / 64;
    for (int tile = blockIdx.x; tile < ntiles; tile += gridDim.x) {
        int row0 = tile * 64;
        __syncthreads();  // sA reuse + (first iter) W visibility
        // load A tile: [64][KC] as float4 units; first K1 from X, rest from G
        for (int idx = tid; idx < 64 * (KC / 4); idx += 256) {
            int r  = idx / (KC / 4);
            int c4 = idx % (KC / 4);
            float4 v = make_float4(0.f, 0.f, 0.f, 0.f);
            int grow = row0 + r;
            if (grow < n) {
                if (c4 < K1 / 4) v = __ldg((const float4*)(X + (size_t)grow * K1) + c4);
                else             v = __ldg((const float4*)(G + (size_t)grow * K1) + (c4 - K1 / 4));
            }
            *(float4*)&sA[r * KCP + c4 * 4] = v;
        }
        __syncthreads();

        float4 acc[TM];
#pragma unroll
        for (int i = 0; i < TM; i++) acc[i] = b4;

#pragma unroll 4
        for (int k = 0; k < KC; k += 4) {
            float4 w0 = *(const float4*)&sW[(k + 0) * OUT + cc * 4];
            float4 w1 = *(const float4*)&sW[(k + 1) * OUT + cc * 4];
            float4 w2 = *(const float4*)&sW[(k + 2) * OUT + cc * 4];
            float4 w3 = *(const float4*)&sW[(k + 3) * OUT + cc * 4];
#pragma unroll
            for (int i = 0; i < TM; i++) {
                int r = rg + i * RG;
                float4 a = *(const float4*)&sA[r * KCP + k];
                acc[i].x = fmaf(a.x, w0.x, fmaf(a.y, w1.x, fmaf(a.z, w2.x, fmaf(a.w, w3.x, acc[i].x))));
                acc[i].y = fmaf(a.x, w0.y, fmaf(a.y, w1.y, fmaf(a.z, w2.y, fmaf(a.w, w3.y, acc[i].y))));
                acc[i].z = fmaf(a.x, w0.z, fmaf(a.y, w1.z, fmaf(a.z, w2.z, fmaf(a.w, w3.z, acc[i].z))));
                acc[i].w = fmaf(a.x, w0.w, fmaf(a.y, w1.w, fmaf(a.z, w2.w, fmaf(a.w, w3.w, acc[i].w))));
            }
        }

        if (ACT == 0) {
            // ReLU epilogue
#pragma unroll
            for (int i = 0; i < TM; i++) {
                int row = row0 + rg + i * RG;
                if (row < n) {
                    float4 o = make_float4(fmaxf(acc[i].x, 0.f), fmaxf(acc[i].y, 0.f),
                                           fmaxf(acc[i].z, 0.f), fmaxf(acc[i].w, 0.f));
                    *(float4*)(Y + (size_t)row * OUT + cc * 4) = o;
                }
            }
        } else {
            // softmax over OUT=64 (16 lanes per row, within half-warps)
#pragma unroll
            for (int i = 0; i < TM; i++) {
                int row = row0 + rg + i * RG;
                float m = fmaxf(fmaxf(acc[i].x, acc[i].y), fmaxf(acc[i].z, acc[i].w));
#pragma unroll
                for (int o = 8; o; o >>= 1) m = fmaxf(m, __shfl_xor_sync(0xffffffffu, m, o));
                float ex = __expf(acc[i].x - m);
                float ey = __expf(acc[i].y - m);
                float ez = __expf(acc[i].z - m);
                float ew = __expf(acc[i].w - m);
                float s = ex + ey + ez + ew;
#pragma unroll
                for (int o = 8; o; o >>= 1) s += __shfl_xor_sync(0xffffffffu, s, o);
                if (row < n) {
                    float inv = 1.0f / s;
                    *(float4*)(Y + (size_t)row * OUT + cc * 4) =
                        make_float4(ex * inv, ey * inv, ez * inv, ew * inv);
                }
            }
        }
    }
}

// ---------------------------------------------------------------------------

extern "C" void kernel_launch(void* const* d_in, const int* in_sizes, int n_in,
                              void* d_out, int out_size) {
    const float* x    = (const float*)d_in[0];
    const int*   src  = (const int*)d_in[1];
    const int*   dst  = (const int*)d_in[2];
    const float* ws1  = (const float*)d_in[3];
    const float* wn1  = (const float*)d_in[4];
    const float* b1   = (const float*)d_in[5];
    const float* ws2  = (const float*)d_in[6];
    const float* wn2  = (const float*)d_in[7];
    const float* b2   = (const float*)d_in[8];
    const float* ws3  = (const float*)d_in[9];
    const float* wn3  = (const float*)d_in[10];
    const float* b3   = (const float*)d_in[11];
    float* out = (float*)d_out;

    int N = in_sizes[0] / 128;
    int E = in_sizes[1];

    // device scratch
    int *deg, *rowptr, *cursor, *colidx;
    float *invdeg, *agg, *h1, *h2;
    cudaGetSymbolAddress((void**)&deg,    g_deg);
    cudaGetSymbolAddress((void**)&rowptr, g_rowptr);
    cudaGetSymbolAddress((void**)&cursor, g_cursor);
    cudaGetSymbolAddress((void**)&colidx, g_colidx);
    cudaGetSymbolAddress((void**)&invdeg, g_invdeg);
    cudaGetSymbolAddress((void**)&agg,    g_agg);
    cudaGetSymbolAddress((void**)&h1,     g_h1);
    cudaGetSymbolAddress((void**)&h2,     g_h2);

    // dynamic smem opt-in (>48KB)
    const int SM1 = (256 * 128) * 4 + 64 * (256 + 4) * 4;  // 131072 + 66560
    const int SM2 = (256 * 64) * 4 + 64 * (256 + 4) * 4;   //  65536 + 66560
    const int SM3 = (128 * 64) * 4 + 64 * (128 + 4) * 4;   //  32768 + 33792
    cudaFuncSetAttribute((const void*)gemm_fused<128, 128, 0>,
                         cudaFuncAttributeMaxDynamicSharedMemorySize, SM1);
    cudaFuncSetAttribute((const void*)gemm_fused<128, 64, 0>,
                         cudaFuncAttributeMaxDynamicSharedMemorySize, SM2);
    cudaFuncSetAttribute((const void*)gemm_fused<64, 64, 1>,
                         cudaFuncAttributeMaxDynamicSharedMemorySize, SM3);

    // ---- CSR build (once; shared by all 3 layers) ----
    zero_int_kernel<<<(N + 255) / 256, 256>>>(deg, N);
    count_deg_kernel<<<(E + 255) / 256, 256>>>(dst, deg, E);
    scan_deg_kernel<<<1, 1024>>>(deg, rowptr, cursor, invdeg, N);
    fill_csr_kernel<<<(E + 255) / 256, 256>>>(src, dst, cursor, colidx, E);

    const int AGG_BLOCKS = 4096;
    const int GEMM_BLOCKS = 304;

    // ---- layer 1: 128 -> 128, ReLU ----
    aggregate_kernel<128><<<AGG_BLOCKS, 256>>>(x, rowptr, colidx, invdeg, agg, N);
    gemm_fused<128, 128, 0><<<GEMM_BLOCKS, 256, SM1>>>(x, agg, ws1, wn1, b1, h1, N);

    // ---- layer 2: 128 -> 64, ReLU ----
    aggregate_kernel<128><<<AGG_BLOCKS, 256>>>(h1, rowptr, colidx, invdeg, agg, N);
    gemm_fused<128, 64, 0><<<GEMM_BLOCKS, 256, SM2>>>(h1, agg, ws2, wn2, b2, h2, N);

    // ---- layer 3: 64 -> 64, softmax ----
    aggregate_kernel<64><<<AGG_BLOCKS, 256>>>(h2, rowptr, colidx, invdeg, agg, N);
    gemm_fused<64, 64, 1><<<GEMM_BLOCKS, 256, SM3>>>(h2, agg, ws3, wn3, b3, out, N);
}

// round 2
// speedup vs baseline: 1.2101x; 1.2101x over previous
#include <cuda_runtime.h>
#include <cuda_bf16.h>
#include <math.h>

// ---------------------------------------------------------------------------
// GraphSAGE (3x SAGEConv mean + ReLU, softmax) on GB300 — round 2.
//  * Project-then-aggregate: per layer, ONE GEMM  A @ [Ws|Wn] -> [S|P],
//    then mean-aggregate P (at OUTPUT width) with fused bias/ReLU/softmax.
//  * GEMM inner loop uses packed fma.rn.f32x2 (FFMA2) with row-pairs:
//    A tile stored k-major (transposed) in smem so a row-pair is one LDS.64;
//    W scalar is packed (w,w) once per col per k, shared across row-pairs.
// ---------------------------------------------------------------------------

#define MAXN 100000
#define MAXE 1600000

typedef unsigned long long ull;

__device__ int   g_deg[MAXN];
__device__ int   g_rowptr[MAXN + 1];
__device__ int   g_cursor[MAXN];
__device__ int   g_colidx[MAXE];
__device__ float g_invdeg[MAXN];
__device__ float g_S[(size_t)MAXN * 128];   // self-projection (+bias)
__device__ float g_P[(size_t)MAXN * 128];   // neighbor-projection
__device__ float g_h[(size_t)MAXN * 128];   // hidden activations (h1 then h2)

#define PK(v, lo, hi)   asm("mov.b64 %0, {%1,%2};" : "=l"(v) : "f"(lo), "f"(hi))
#define UNPK(lo, hi, v) asm("mov.b64 {%0,%1}, %2;" : "=f"(lo), "=f"(hi) : "l"(v))
#define FMA2(acc, a, w) asm("fma.rn.f32x2 %0, %1, %2, %0;" : "+l"(acc) : "l"(a), "l"(w))

// ---------------------------- CSR construction ----------------------------

__global__ void zero_int_kernel(int* p, int n) {
    int i = blockIdx.x * blockDim.x + threadIdx.x;
    if (i < n) p[i] = 0;
}

__global__ void count_deg_kernel(const int* __restrict__ dst, int* __restrict__ deg, int E) {
    int e = blockIdx.x * blockDim.x + threadIdx.x;
    if (e < E) atomicAdd(&deg[__ldg(&dst[e])], 1);
}

__global__ void scan_deg_kernel(const int* __restrict__ deg, int* __restrict__ rowptr,
                                int* __restrict__ cursor, float* __restrict__ invdeg, int n) {
    __shared__ int ssum[1024];
    int tid = threadIdx.x;
    int chunk = (n + 1023) / 1024;
    int lo = tid * chunk;
    int hi = lo + chunk; if (hi > n) hi = n;
    if (lo > n) lo = n;

    int sum = 0;
    for (int i = lo; i < hi; ++i) sum += deg[i];
    ssum[tid] = sum;
    __syncthreads();
    for (int off = 1; off < 1024; off <<= 1) {
        int v = (tid >= off) ? ssum[tid - off] : 0;
        __syncthreads();
        ssum[tid] += v;
        __syncthreads();
    }
    int run = ssum[tid] - sum;  // exclusive prefix
    for (int i = lo; i < hi; ++i) {
        rowptr[i] = run;
        cursor[i] = run;
        float d = (float)deg[i];
        invdeg[i] = 1.0f / fmaxf(d, 1.0f);
        run += deg[i];
    }
    if (tid == 1023) rowptr[n] = ssum[1023];
}

__global__ void fill_csr_kernel(const int* __restrict__ src, const int* __restrict__ dst,
                                int* __restrict__ cursor, int* __restrict__ colidx, int E) {
    int e = blockIdx.x * blockDim.x + threadIdx.x;
    if (e < E) {
        int d = __ldg(&dst[e]);
        int p = atomicAdd(&cursor[d], 1);
        colidx[p] = __ldg(&src[e]);
    }
}

// ------------------- aggregation (mean) with fused epilogue ----------------
// warp per node. Y[i] = act( S[i] + mean_{j in N(i)} P[j] )
// ACT: 0 = ReLU, 1 = row softmax (D==64 only).

template <int D, int ACT>
__global__ void aggregate_ep(const float* __restrict__ P, const float* __restrict__ S,
                             const int* __restrict__ rowptr, const int* __restrict__ colidx,
                             const float* __restrict__ invdeg, float* __restrict__ Y, int n) {
    int warp = (blockIdx.x * blockDim.x + threadIdx.x) >> 5;
    int lane = threadIdx.x & 31;
    int nwarps = (gridDim.x * blockDim.x) >> 5;

    for (int i = warp; i < n; i += nwarps) {
        int s = __ldg(&rowptr[i]);
        int e = __ldg(&rowptr[i + 1]);
        float inv = __ldg(&invdeg[i]);

        if (D == 128) {
            float4 acc = make_float4(0.f, 0.f, 0.f, 0.f);
            int j = s;
            for (; j + 3 < e; j += 4) {
                int c0 = __ldg(&colidx[j]);
                int c1 = __ldg(&colidx[j + 1]);
                int c2 = __ldg(&colidx[j + 2]);
                int c3 = __ldg(&colidx[j + 3]);
                float4 v0 = __ldg((const float4*)(P + (size_t)c0 * D) + lane);
                float4 v1 = __ldg((const float4*)(P + (size_t)c1 * D) + lane);
                float4 v2 = __ldg((const float4*)(P + (size_t)c2 * D) + lane);
                float4 v3 = __ldg((const float4*)(P + (size_t)c3 * D) + lane);
                acc.x += (v0.x + v1.x) + (v2.x + v3.x);
                acc.y += (v0.y + v1.y) + (v2.y + v3.y);
                acc.z += (v0.z + v1.z) + (v2.z + v3.z);
                acc.w += (v0.w + v1.w) + (v2.w + v3.w);
            }
            for (; j < e; ++j) {
                int c0 = __ldg(&colidx[j]);
                float4 v0 = __ldg((const float4*)(P + (size_t)c0 * D) + lane);
                acc.x += v0.x; acc.y += v0.y; acc.z += v0.z; acc.w += v0.w;
            }
            float4 sv = __ldg((const float4*)(S + (size_t)i * D) + lane);
            float4 o;
            o.x = fmaxf(fmaf(acc.x, inv, sv.x), 0.f);
            o.y = fmaxf(fmaf(acc.y, inv, sv.y), 0.f);
            o.z = fmaxf(fmaf(acc.z, inv, sv.z), 0.f);
            o.w = fmaxf(fmaf(acc.w, inv, sv.w), 0.f);
            ((float4*)(Y + (size_t)i * D))[lane] = o;
        } else {  // D == 64
            float2 acc = make_float2(0.f, 0.f);
            int j = s;
            for (; j + 3 < e; j += 4) {
                int c0 = __ldg(&colidx[j]);
                int c1 = __ldg(&colidx[j + 1]);
                int c2 = __ldg(&colidx[j + 2]);
                int c3 = __ldg(&colidx[j + 3]);
                float2 v0 = __ldg((const float2*)(P + (size_t)c0 * D) + lane);
                float2 v1 = __ldg((const float2*)(P + (size_t)c1 * D) + lane);
                float2 v2 = __ldg((const float2*)(P + (size_t)c2 * D) + lane);
                float2 v3 = __ldg((const float2*)(P + (size_t)c3 * D) + lane);
                acc.x += (v0.x + v1.x) + (v2.x + v3.x);
                acc.y += (v0.y + v1.y) + (v2.y + v3.y);
            }
            for (; j < e; ++j) {
                int c0 = __ldg(&colidx[j]);
                float2 v0 = __ldg((const float2*)(P + (size_t)c0 * D) + lane);
                acc.x += v0.x; acc.y += v0.y;
            }
            float2 sv = __ldg((const float2*)(S + (size_t)i * D) + lane);
            float tx = fmaf(acc.x, inv, sv.x);
            float ty = fmaf(acc.y, inv, sv.y);
            if (ACT == 0) {
                float2 o = make_float2(fmaxf(tx, 0.f), fmaxf(ty, 0.f));
                ((float2*)(Y + (size_t)i * D))[lane] = o;
            } else {
                // softmax over the 64-wide row (32 lanes x 2)
                float m = fmaxf(tx, ty);
#pragma unroll
                for (int o = 16; o; o >>= 1) m = fmaxf(m, __shfl_xor_sync(0xffffffffu, m, o));
                float ex = __expf(tx - m);
                float ey = __expf(ty - m);
                float sm = ex + ey;
#pragma unroll
                for (int o = 16; o; o >>= 1) sm += __shfl_xor_sync(0xffffffffu, sm, o);
                float rinv = 1.0f / sm;
                ((float2*)(Y + (size_t)i * D))[lane] = make_float2(ex * rinv, ey * rinv);
            }
        }
    }
}

// ---------------------------- projection GEMM ----------------------------
// [S|P](64-row tile) = A @ [Ws|Wn]; bias added to S half only.
// sW [KC][OUT] resident; A tile stored TRANSPOSED: sAT[KC][64] so that a
// row-pair (2 adjacent output rows) is one aligned LDS.64 -> fma.rn.f32x2.
// THREADS=512. CPG = OUT/4 col-groups, RG = 512/CPG row-groups, TM = 64/RG.

template <int KC, int HF>   // HF = out_f; OUT = 2*HF
__global__ __launch_bounds__(512, 1) void gemm_proj(
    const float* __restrict__ A, const float* __restrict__ Ws,
    const float* __restrict__ Wn, const float* __restrict__ bias,
    float* __restrict__ Sout, float* __restrict__ Pout, int n) {
    constexpr int OUT = 2 * HF;
    constexpr int CPG = OUT / 4;
    constexpr int RG  = 512 / CPG;
    constexpr int TM  = 64 / RG;
    constexpr int TP  = TM / 2;

    extern __shared__ float sm[];
    float* sW  = sm;               // [KC][OUT]
    float* sAT = sm + KC * OUT;    // [KC][64], k-major

    int tid = threadIdx.x;

    // load W concat: cols [0,HF)=Ws, [HF,OUT)=Wn
    for (int idx = tid * 4; idx < KC * HF; idx += 512 * 4) {
        int k = idx / HF;
        int c = idx % HF;
        *(float4*)&sW[k * OUT + c]      = *(const float4*)&Ws[idx];
        *(float4*)&sW[k * OUT + HF + c] = *(const float4*)&Wn[idx];
    }

    int cc  = tid % CPG;
    int cc4 = cc * 4;
    int rg  = tid / CPG;
    int rbase = rg * TM;

    float4 b4 = make_float4(0.f, 0.f, 0.f, 0.f);
    if (cc4 < HF) b4 = __ldg((const float4*)bias + cc);

    float* OP = (cc4 < HF) ? Sout : Pout;
    int    co = (cc4 < HF) ? cc4 : (cc4 - HF);

    ull bias2[4];
    PK(bias2[0], b4.x, b4.x); PK(bias2[1], b4.y, b4.y);
    PK(bias2[2], b4.z, b4.z); PK(bias2[3], b4.w, b4.w);

    int ntiles = (n + 63) / 64;
    for (int tile = blockIdx.x; tile < ntiles; tile += gridDim.x) {
        int row0 = tile * 64;
        __syncthreads();  // protect sAT reuse (and first-iter sW)
        // A tile -> transposed smem. thread: r = idx&63, k4 = idx>>6
        for (int idx = tid; idx < 64 * (KC / 4); idx += 512) {
            int r  = idx & 63;
            int k4 = idx >> 6;
            float4 v = make_float4(0.f, 0.f, 0.f, 0.f);
            int grow = row0 + r;
            if (grow < n) v = __ldg((const float4*)(A + (size_t)grow * KC) + k4);
            sAT[(k4 * 4 + 0) * 64 + r] = v.x;
            sAT[(k4 * 4 + 1) * 64 + r] = v.y;
            sAT[(k4 * 4 + 2) * 64 + r] = v.z;
            sAT[(k4 * 4 + 3) * 64 + r] = v.w;
        }
        __syncthreads();

        ull acc[TP][4];
#pragma unroll
        for (int p = 0; p < TP; ++p) {
            acc[p][0] = bias2[0]; acc[p][1] = bias2[1];
            acc[p][2] = bias2[2]; acc[p][3] = bias2[3];
        }

#pragma unroll 2
        for (int k = 0; k < KC; ++k) {
            float4 w = *(const float4*)&sW[k * OUT + cc4];
            ull w0, w1, w2, w3;
            PK(w0, w.x, w.x); PK(w1, w.y, w.y);
            PK(w2, w.z, w.z); PK(w3, w.w, w.w);
            const ull* ap = (const ull*)&sAT[k * 64] + (rbase >> 1);
#pragma unroll
            for (int p = 0; p < TP; ++p) {
                ull a = ap[p];
                FMA2(acc[p][0], a, w0);
                FMA2(acc[p][1], a, w1);
                FMA2(acc[p][2], a, w2);
                FMA2(acc[p][3], a, w3);
            }
        }

        // epilogue: unpack row-pairs, store float4 per row into S or P
#pragma unroll
        for (int p = 0; p < TP; ++p) {
            float l0, h0, l1, h1, l2, h2, l3, h3;
            UNPK(l0, h0, acc[p][0]); UNPK(l1, h1, acc[p][1]);
            UNPK(l2, h2, acc[p][2]); UNPK(l3, h3, acc[p][3]);
            int rA = row0 + rbase + 2 * p;
            if (rA < n)
                *(float4*)(OP + (size_t)rA * HF + co) = make_float4(l0, l1, l2, l3);
            if (rA + 1 < n)
                *(float4*)(OP + (size_t)(rA + 1) * HF + co) = make_float4(h0, h1, h2, h3);
        }
    }
}

// ---------------------------------------------------------------------------

extern "C" void kernel_launch(void* const* d_in, const int* in_sizes, int n_in,
                              void* d_out, int out_size) {
    const float* x   = (const float*)d_in[0];
    const int*   src = (const int*)d_in[1];
    const int*   dst = (const int*)d_in[2];
    const float* ws1 = (const float*)d_in[3];
    const float* wn1 = (const float*)d_in[4];
    const float* b1  = (const float*)d_in[5];
    const float* ws2 = (const float*)d_in[6];
    const float* wn2 = (const float*)d_in[7];
    const float* b2  = (const float*)d_in[8];
    const float* ws3 = (const float*)d_in[9];
    const float* wn3 = (const float*)d_in[10];
    const float* b3  = (const float*)d_in[11];
    float* out = (float*)d_out;

    int N = in_sizes[0] / 128;
    int E = in_sizes[1];

    int *deg, *rowptr, *cursor, *colidx;
    float *invdeg, *Sb, *Pb, *hb;
    cudaGetSymbolAddress((void**)&deg,    g_deg);
    cudaGetSymbolAddress((void**)&rowptr, g_rowptr);
    cudaGetSymbolAddress((void**)&cursor, g_cursor);
    cudaGetSymbolAddress((void**)&colidx, g_colidx);
    cudaGetSymbolAddress((void**)&invdeg, g_invdeg);
    cudaGetSymbolAddress((void**)&Sb,     g_S);
    cudaGetSymbolAddress((void**)&Pb,     g_P);
    cudaGetSymbolAddress((void**)&hb,     g_h);

    const int SM1 = (128 * 256 + 128 * 64) * 4;  // 163840
    const int SM2 = (128 * 128 + 128 * 64) * 4;  //  98304
    const int SM3 = (64 * 128 + 64 * 64) * 4;    //  49152
    cudaFuncSetAttribute((const void*)gemm_proj<128, 128>,
                         cudaFuncAttributeMaxDynamicSharedMemorySize, SM1);
    cudaFuncSetAttribute((const void*)gemm_proj<128, 64>,
                         cudaFuncAttributeMaxDynamicSharedMemorySize, SM2);
    cudaFuncSetAttribute((const void*)gemm_proj<64, 64>,
                         cudaFuncAttributeMaxDynamicSharedMemorySize, SM3);

    // ---- CSR build (once; shared by all 3 layers) ----
    zero_int_kernel<<<(N + 255) / 256, 256>>>(deg, N);
    count_deg_kernel<<<(E + 255) / 256, 256>>>(dst, deg, E);
    scan_deg_kernel<<<1, 1024>>>(deg, rowptr, cursor, invdeg, N);
    fill_csr_kernel<<<(E + 255) / 256, 256>>>(src, dst, cursor, colidx, E);

    const int AGG_BLOCKS = 2048;

    // ---- layer 1: X(128) -> [S1|P1](128 each); h1 = relu(S1 + agg(P1)) ----
    gemm_proj<128, 128><<<148, 512, SM1>>>(x, ws1, wn1, b1, Sb, Pb, N);
    aggregate_ep<128, 0><<<AGG_BLOCKS, 256>>>(Pb, Sb, rowptr, colidx, invdeg, hb, N);

    // ---- layer 2: h1(128) -> [S2|P2](64 each); h2 = relu(S2 + agg(P2)) ----
    gemm_proj<128, 64><<<296, 512, SM2>>>(hb, ws2, wn2, b2, Sb, Pb, N);
    aggregate_ep<64, 0><<<AGG_BLOCKS, 256>>>(Pb, Sb, rowptr, colidx, invdeg, hb, N);

    // ---- layer 3: h2(64) -> [S3|P3](64 each); out = softmax(S3 + agg(P3)) ----
    gemm_proj<64, 64><<<444, 512, SM3>>>(hb, ws3, wn3, b3, Sb, Pb, N);
    aggregate_ep<64, 1><<<AGG_BLOCKS, 256>>>(Pb, Sb, rowptr, colidx, invdeg, out, N);
}

// round 3
// speedup vs baseline: 1.6819x; 1.3899x over previous
#include <cuda_runtime.h>
#include <cuda_fp16.h>
#include <cuda_bf16.h>
#include <math.h>

// ---------------------------------------------------------------------------
// GraphSAGE (3x SAGEConv mean + ReLU, softmax) on GB300 — round 3.
//  * Project-then-aggregate: per layer ONE GEMM  A @ [Ws|Wn] -> [S(fp32)|P(fp16)]
//  * P stored fp16 -> neighbor-gather traffic halved; fp32 accumulate.
//  * CSR build overlapped with layer-1 GEMM on a forked capture stream.
// ---------------------------------------------------------------------------

#define MAXN 100000
#define MAXE 1600000

typedef unsigned long long ull;

__device__ int    g_deg[MAXN];
__device__ int    g_rowptr[MAXN + 1];
__device__ int    g_cursor[MAXN];
__device__ int    g_colidx[MAXE];
__device__ float  g_invdeg[MAXN];
__device__ float  g_S[(size_t)MAXN * 128];     // self-projection (+bias), fp32
__device__ __half g_P[(size_t)MAXN * 128];     // neighbor-projection, fp16
__device__ float  g_h[(size_t)MAXN * 128];     // hidden activations

#define PK(v, lo, hi)   asm("mov.b64 %0, {%1,%2};" : "=l"(v) : "f"(lo), "f"(hi))
#define UNPK(lo, hi, v) asm("mov.b64 {%0,%1}, %2;" : "=f"(lo), "=f"(hi) : "l"(v))
#define FMA2(acc, a, w) asm("fma.rn.f32x2 %0, %1, %2, %0;" : "+l"(acc) : "l"(a), "l"(w))

// ---------------------------- CSR construction ----------------------------

__global__ void zero_int_kernel(int* p, int n) {
    int i = blockIdx.x * blockDim.x + threadIdx.x;
    if (i < n) p[i] = 0;
}

__global__ void count_deg_kernel(const int* __restrict__ dst, int* __restrict__ deg, int E) {
    int e = blockIdx.x * blockDim.x + threadIdx.x;
    if (e < E) atomicAdd(&deg[__ldg(&dst[e])], 1);
}

__global__ void scan_deg_kernel(const int* __restrict__ deg, int* __restrict__ rowptr,
                                int* __restrict__ cursor, float* __restrict__ invdeg, int n) {
    __shared__ int ssum[1024];
    int tid = threadIdx.x;
    int chunk = (n + 1023) / 1024;
    int lo = tid * chunk;
    int hi = lo + chunk; if (hi > n) hi = n;
    if (lo > n) lo = n;

    int sum = 0;
    for (int i = lo; i < hi; ++i) sum += deg[i];
    ssum[tid] = sum;
    __syncthreads();
    for (int off = 1; off < 1024; off <<= 1) {
        int v = (tid >= off) ? ssum[tid - off] : 0;
        __syncthreads();
        ssum[tid] += v;
        __syncthreads();
    }
    int run = ssum[tid] - sum;  // exclusive prefix
    for (int i = lo; i < hi; ++i) {
        rowptr[i] = run;
        cursor[i] = run;
        float d = (float)deg[i];
        invdeg[i] = 1.0f / fmaxf(d, 1.0f);
        run += deg[i];
    }
    if (tid == 1023) rowptr[n] = ssum[1023];
}

__global__ void fill_csr_kernel(const int* __restrict__ src, const int* __restrict__ dst,
                                int* __restrict__ cursor, int* __restrict__ colidx, int E) {
    int e = blockIdx.x * blockDim.x + threadIdx.x;
    if (e < E) {
        int d = __ldg(&dst[e]);
        int p = atomicAdd(&cursor[d], 1);
        colidx[p] = __ldg(&src[e]);
    }
}

// ------------------- aggregation (mean) with fused epilogue ----------------
// warp per node. Y[i] = act( S[i] + mean_{j in N(i)} P[j] ), P in fp16.
// ACT: 0 = ReLU, 1 = row softmax (D==64 only).

template <int D, int ACT>
__global__ void aggregate_ep(const __half* __restrict__ P, const float* __restrict__ S,
                             const int* __restrict__ rowptr, const int* __restrict__ colidx,
                             const float* __restrict__ invdeg, float* __restrict__ Y, int n) {
    int warp = (blockIdx.x * blockDim.x + threadIdx.x) >> 5;
    int lane = threadIdx.x & 31;
    int nwarps = (gridDim.x * blockDim.x) >> 5;

    for (int i = warp; i < n; i += nwarps) {
        int s = __ldg(&rowptr[i]);
        int e = __ldg(&rowptr[i + 1]);
        float inv = __ldg(&invdeg[i]);

        if (D == 128) {
            float4 acc = make_float4(0.f, 0.f, 0.f, 0.f);
            int j = s;
            for (; j + 3 < e; j += 4) {
                int c0 = __ldg(&colidx[j]);
                int c1 = __ldg(&colidx[j + 1]);
                int c2 = __ldg(&colidx[j + 2]);
                int c3 = __ldg(&colidx[j + 3]);
                uint2 u0 = __ldg((const uint2*)(P + (size_t)c0 * 128) + lane);
                uint2 u1 = __ldg((const uint2*)(P + (size_t)c1 * 128) + lane);
                uint2 u2 = __ldg((const uint2*)(P + (size_t)c2 * 128) + lane);
                uint2 u3 = __ldg((const uint2*)(P + (size_t)c3 * 128) + lane);
                float2 a0 = __half22float2(*(const __half2*)&u0.x);
                float2 b0 = __half22float2(*(const __half2*)&u0.y);
                float2 a1 = __half22float2(*(const __half2*)&u1.x);
                float2 b1 = __half22float2(*(const __half2*)&u1.y);
                float2 a2 = __half22float2(*(const __half2*)&u2.x);
                float2 b2 = __half22float2(*(const __half2*)&u2.y);
                float2 a3 = __half22float2(*(const __half2*)&u3.x);
                float2 b3 = __half22float2(*(const __half2*)&u3.y);
                acc.x += (a0.x + a1.x) + (a2.x + a3.x);
                acc.y += (a0.y + a1.y) + (a2.y + a3.y);
                acc.z += (b0.x + b1.x) + (b2.x + b3.x);
                acc.w += (b0.y + b1.y) + (b2.y + b3.y);
            }
            for (; j < e; ++j) {
                int c0 = __ldg(&colidx[j]);
                uint2 u0 = __ldg((const uint2*)(P + (size_t)c0 * 128) + lane);
                float2 a0 = __half22float2(*(const __half2*)&u0.x);
                float2 b0 = __half22float2(*(const __half2*)&u0.y);
                acc.x += a0.x; acc.y += a0.y; acc.z += b0.x; acc.w += b0.y;
            }
            float4 sv = __ldg((const float4*)(S + (size_t)i * 128) + lane);
            float4 o;
            o.x = fmaxf(fmaf(acc.x, inv, sv.x), 0.f);
            o.y = fmaxf(fmaf(acc.y, inv, sv.y), 0.f);
            o.z = fmaxf(fmaf(acc.z, inv, sv.z), 0.f);
            o.w = fmaxf(fmaf(acc.w, inv, sv.w), 0.f);
            ((float4*)(Y + (size_t)i * 128))[lane] = o;
        } else {  // D == 64
            float2 acc = make_float2(0.f, 0.f);
            int j = s;
            for (; j + 3 < e; j += 4) {
                int c0 = __ldg(&colidx[j]);
                int c1 = __ldg(&colidx[j + 1]);
                int c2 = __ldg(&colidx[j + 2]);
                int c3 = __ldg(&colidx[j + 3]);
                unsigned u0 = __ldg((const unsigned*)(P + (size_t)c0 * 64) + lane);
                unsigned u1 = __ldg((const unsigned*)(P + (size_t)c1 * 64) + lane);
                unsigned u2 = __ldg((const unsigned*)(P + (size_t)c2 * 64) + lane);
                unsigned u3 = __ldg((const unsigned*)(P + (size_t)c3 * 64) + lane);
                float2 f0 = __half22float2(*(const __half2*)&u0);
                float2 f1 = __half22float2(*(const __half2*)&u1);
                float2 f2 = __half22float2(*(const __half2*)&u2);
                float2 f3 = __half22float2(*(const __half2*)&u3);
                acc.x += (f0.x + f1.x) + (f2.x + f3.x);
                acc.y += (f0.y + f1.y) + (f2.y + f3.y);
            }
            for (; j < e; ++j) {
                int c0 = __ldg(&colidx[j]);
                unsigned u0 = __ldg((const unsigned*)(P + (size_t)c0 * 64) + lane);
                float2 f0 = __half22float2(*(const __half2*)&u0);
                acc.x += f0.x; acc.y += f0.y;
            }
            float2 sv = __ldg((const float2*)(S + (size_t)i * 64) + lane);
            float tx = fmaf(acc.x, inv, sv.x);
            float ty = fmaf(acc.y, inv, sv.y);
            if (ACT == 0) {
                ((float2*)(Y + (size_t)i * 64))[lane] = make_float2(fmaxf(tx, 0.f), fmaxf(ty, 0.f));
            } else {
                float m = fmaxf(tx, ty);
#pragma unroll
                for (int o = 16; o; o >>= 1) m = fmaxf(m, __shfl_xor_sync(0xffffffffu, m, o));
                float ex = __expf(tx - m);
                float ey = __expf(ty - m);
                float sm = ex + ey;
#pragma unroll
                for (int o = 16; o; o >>= 1) sm += __shfl_xor_sync(0xffffffffu, sm, o);
                float rinv = 1.0f / sm;
                ((float2*)(Y + (size_t)i * 64))[lane] = make_float2(ex * rinv, ey * rinv);
            }
        }
    }
}

// ---------------------------- projection GEMM ----------------------------
// [S|P](64-row tile) = A @ [Ws|Wn]; bias added to S half only.
// sW [KC][OUT] resident; A tile stored TRANSPOSED: sAT[KC][64] so a row-pair
// is one LDS.64 -> fma.rn.f32x2. S half stored fp32, P half stored fp16.

template <int KC, int HF>   // HF = out_f; OUT = 2*HF
__global__ __launch_bounds__(512, 1) void gemm_proj(
    const float* __restrict__ A, const float* __restrict__ Ws,
    const float* __restrict__ Wn, const float* __restrict__ bias,
    float* __restrict__ Sout, __half* __restrict__ Pout, int n) {
    constexpr int OUT = 2 * HF;
    constexpr int CPG = OUT / 4;
    constexpr int RG  = 512 / CPG;
    constexpr int TM  = 64 / RG;
    constexpr int TP  = TM / 2;

    extern __shared__ float sm[];
    float* sW  = sm;               // [KC][OUT]
    float* sAT = sm + KC * OUT;    // [KC][64], k-major

    int tid = threadIdx.x;

    for (int idx = tid * 4; idx < KC * HF; idx += 512 * 4) {
        int k = idx / HF;
        int c = idx % HF;
        *(float4*)&sW[k * OUT + c]      = *(const float4*)&Ws[idx];
        *(float4*)&sW[k * OUT + HF + c] = *(const float4*)&Wn[idx];
    }

    int cc  = tid % CPG;
    int cc4 = cc * 4;
    int rg  = tid / CPG;
    int rbase = rg * TM;
    bool isS = (cc4 < HF);
    int co = isS ? cc4 : (cc4 - HF);

    float4 b4 = make_float4(0.f, 0.f, 0.f, 0.f);
    if (isS) b4 = __ldg((const float4*)bias + cc);

    ull bias2[4];
    PK(bias2[0], b4.x, b4.x); PK(bias2[1], b4.y, b4.y);
    PK(bias2[2], b4.z, b4.z); PK(bias2[3], b4.w, b4.w);

    int ntiles = (n + 63) / 64;
    for (int tile = blockIdx.x; tile < ntiles; tile += gridDim.x) {
        int row0 = tile * 64;
        __syncthreads();  // protect sAT reuse (and first-iter sW)
        for (int idx = tid; idx < 64 * (KC / 4); idx += 512) {
            int r  = idx & 63;
            int k4 = idx >> 6;
            float4 v = make_float4(0.f, 0.f, 0.f, 0.f);
            int grow = row0 + r;
            if (grow < n) v = __ldg((const float4*)(A + (size_t)grow * KC) + k4);
            sAT[(k4 * 4 + 0) * 64 + r] = v.x;
            sAT[(k4 * 4 + 1) * 64 + r] = v.y;
            sAT[(k4 * 4 + 2) * 64 + r] = v.z;
            sAT[(k4 * 4 + 3) * 64 + r] = v.w;
        }
        __syncthreads();

        ull acc[TP][4];
#pragma unroll
        for (int p = 0; p < TP; ++p) {
            acc[p][0] = bias2[0]; acc[p][1] = bias2[1];
            acc[p][2] = bias2[2]; acc[p][3] = bias2[3];
        }

#pragma unroll 2
        for (int k = 0; k < KC; ++k) {
            float4 w = *(const float4*)&sW[k * OUT + cc4];
            ull w0, w1, w2, w3;
            PK(w0, w.x, w.x); PK(w1, w.y, w.y);
            PK(w2, w.z, w.z); PK(w3, w.w, w.w);
            const ull* ap = (const ull*)&sAT[k * 64] + (rbase >> 1);
#pragma unroll
            for (int p = 0; p < TP; ++p) {
                ull a = ap[p];
                FMA2(acc[p][0], a, w0);
                FMA2(acc[p][1], a, w1);
                FMA2(acc[p][2], a, w2);
                FMA2(acc[p][3], a, w3);
            }
        }

#pragma unroll
        for (int p = 0; p < TP; ++p) {
            float l0, h0, l1, h1, l2, h2, l3, h3;
            UNPK(l0, h0, acc[p][0]); UNPK(l1, h1, acc[p][1]);
            UNPK(l2, h2, acc[p][2]); UNPK(l3, h3, acc[p][3]);
            int rA = row0 + rbase + 2 * p;
            if (isS) {
                if (rA < n)
                    *(float4*)(Sout + (size_t)rA * HF + co) = make_float4(l0, l1, l2, l3);
                if (rA + 1 < n)
                    *(float4*)(Sout + (size_t)(rA + 1) * HF + co) = make_float4(h0, h1, h2, h3);
            } else {
                if (rA < n) {
                    __half2 p01 = __floats2half2_rn(l0, l1);
                    __half2 p23 = __floats2half2_rn(l2, l3);
                    *(uint2*)(Pout + (size_t)rA * HF + co) =
                        make_uint2(*(unsigned*)&p01, *(unsigned*)&p23);
                }
                if (rA + 1 < n) {
                    __half2 p01 = __floats2half2_rn(h0, h1);
                    __half2 p23 = __floats2half2_rn(h2, h3);
                    *(uint2*)(Pout + (size_t)(rA + 1) * HF + co) =
                        make_uint2(*(unsigned*)&p01, *(unsigned*)&p23);
                }
            }
        }
    }
}

// ---------------------------------------------------------------------------

extern "C" void kernel_launch(void* const* d_in, const int* in_sizes, int n_in,
                              void* d_out, int out_size) {
    const float* x   = (const float*)d_in[0];
    const int*   src = (const int*)d_in[1];
    const int*   dst = (const int*)d_in[2];
    const float* ws1 = (const float*)d_in[3];
    const float* wn1 = (const float*)d_in[4];
    const float* b1  = (const float*)d_in[5];
    const float* ws2 = (const float*)d_in[6];
    const float* wn2 = (const float*)d_in[7];
    const float* b2  = (const float*)d_in[8];
    const float* ws3 = (const float*)d_in[9];
    const float* wn3 = (const float*)d_in[10];
    const float* b3  = (const float*)d_in[11];
    float* out = (float*)d_out;

    int N = in_sizes[0] / 128;
    int E = in_sizes[1];

    int *deg, *rowptr, *cursor, *colidx;
    float *invdeg, *Sb, *hb;
    __half* Pb;
    cudaGetSymbolAddress((void**)&deg,    g_deg);
    cudaGetSymbolAddress((void**)&rowptr, g_rowptr);
    cudaGetSymbolAddress((void**)&cursor, g_cursor);
    cudaGetSymbolAddress((void**)&colidx, g_colidx);
    cudaGetSymbolAddress((void**)&invdeg, g_invdeg);
    cudaGetSymbolAddress((void**)&Sb,     g_S);
    cudaGetSymbolAddress((void**)&Pb,     g_P);
    cudaGetSymbolAddress((void**)&hb,     g_h);

    const int SM1 = (128 * 256 + 128 * 64) * 4;  // 163840
    const int SM2 = (128 * 128 + 128 * 64) * 4;  //  98304
    const int SM3 = (64 * 128 + 64 * 64) * 4;    //  49152
    cudaFuncSetAttribute((const void*)gemm_proj<128, 128>,
                         cudaFuncAttributeMaxDynamicSharedMemorySize, SM1);
    cudaFuncSetAttribute((const void*)gemm_proj<128, 64>,
                         cudaFuncAttributeMaxDynamicSharedMemorySize, SM2);
    cudaFuncSetAttribute((const void*)gemm_proj<64, 64>,
                         cudaFuncAttributeMaxDynamicSharedMemorySize, SM3);

    // side stream for CSR build, forked/joined via events (capture-safe)
    static cudaStream_t s_csr = 0;
    static cudaEvent_t e_fork = 0, e_join = 0;
    if (!s_csr) {
        cudaStreamCreateWithFlags(&s_csr, cudaStreamNonBlocking);
        cudaEventCreateWithFlags(&e_fork, cudaEventDisableTiming);
        cudaEventCreateWithFlags(&e_join, cudaEventDisableTiming);
    }

    // ---- fork: CSR build on side stream, layer-1 GEMM on main stream ----
    cudaEventRecord(e_fork, 0);
    cudaStreamWaitEvent(s_csr, e_fork, 0);
    zero_int_kernel<<<(N + 255) / 256, 256, 0, s_csr>>>(deg, N);
    count_deg_kernel<<<(E + 255) / 256, 256, 0, s_csr>>>(dst, deg, E);
    scan_deg_kernel<<<1, 1024, 0, s_csr>>>(deg, rowptr, cursor, invdeg, N);
    fill_csr_kernel<<<(E + 255) / 256, 256, 0, s_csr>>>(src, dst, cursor, colidx, E);
    cudaEventRecord(e_join, s_csr);

    gemm_proj<128, 128><<<148, 512, SM1>>>(x, ws1, wn1, b1, Sb, Pb, N);
    cudaStreamWaitEvent(0, e_join, 0);   // join before first aggregation

    const int AGG_BLOCKS = 2048;

    // ---- layer 1 ----
    aggregate_ep<128, 0><<<AGG_BLOCKS, 256>>>(Pb, Sb, rowptr, colidx, invdeg, hb, N);
    // ---- layer 2 ----
    gemm_proj<128, 64><<<296, 512, SM2>>>(hb, ws2, wn2, b2, Sb, Pb, N);
    aggregate_ep<64, 0><<<AGG_BLOCKS, 256>>>(Pb, Sb, rowptr, colidx, invdeg, hb, N);
    // ---- layer 3 ----
    gemm_proj<64, 64><<<444, 512, SM3>>>(hb, ws3, wn3, b3, Sb, Pb, N);
    aggregate_ep<64, 1><<<AGG_BLOCKS, 256>>>(Pb, Sb, rowptr, colidx, invdeg, out, N);
}

// round 4
// speedup vs baseline: 1.7449x; 1.0375x over previous
#include <cuda_runtime.h>
#include <cuda_fp16.h>
#include <cuda_bf16.h>
#include <math.h>

// ---------------------------------------------------------------------------
// GraphSAGE (3x SAGEConv mean + ReLU, softmax) on GB300 — round 4.
//  * GEMMs on tensor cores: split-fp16 (hi+lo) mma.sync m16n8k16, fp32 accum.
//    A@W = Ah*Wh + Ah*Wl + Al*Wh  (error ~1e-6 relative).
//  * Project-then-aggregate; P stored fp16; CSR overlapped with layer-1 GEMM.
// ---------------------------------------------------------------------------

#define MAXN 100000
#define MAXE 1600000

__device__ int    g_deg[MAXN];
__device__ int    g_rowptr[MAXN + 1];
__device__ int    g_cursor[MAXN];
__device__ int    g_colidx[MAXE];
__device__ float  g_invdeg[MAXN];
__device__ float  g_S[(size_t)MAXN * 128];     // self-projection (+bias), fp32
__device__ __half g_P[(size_t)MAXN * 128];     // neighbor-projection, fp16
__device__ float  g_h[(size_t)MAXN * 128];     // hidden activations

static __device__ __forceinline__ unsigned su32(const void* p) {
    return (unsigned)__cvta_generic_to_shared(p);
}

#define LDSM_X4(r, a)                                                          \
    asm volatile("ldmatrix.sync.aligned.m8n8.x4.shared.b16 {%0,%1,%2,%3}, [%4];" \
                 : "=r"((r)[0]), "=r"((r)[1]), "=r"((r)[2]), "=r"((r)[3]) : "r"(a))

#define LDSM_X4T(r, a)                                                         \
    asm volatile("ldmatrix.sync.aligned.m8n8.x4.trans.shared.b16 {%0,%1,%2,%3}, [%4];" \
                 : "=r"((r)[0]), "=r"((r)[1]), "=r"((r)[2]), "=r"((r)[3]) : "r"(a))

#define MMA16816(d, a, b0, b1)                                                 \
    asm volatile("mma.sync.aligned.m16n8k16.row.col.f32.f16.f16.f32 "          \
                 "{%0,%1,%2,%3}, {%4,%5,%6,%7}, {%8,%9}, {%0,%1,%2,%3};"       \
                 : "+f"((d)[0]), "+f"((d)[1]), "+f"((d)[2]), "+f"((d)[3])      \
                 : "r"((a)[0]), "r"((a)[1]), "r"((a)[2]), "r"((a)[3]),         \
                   "r"(b0), "r"(b1))

// ---------------------------- CSR construction ----------------------------

__global__ void zero_int_kernel(int* p, int n) {
    int i = blockIdx.x * blockDim.x + threadIdx.x;
    if (i < n) p[i] = 0;
}

__global__ void count_deg_kernel(const int* __restrict__ dst, int* __restrict__ deg, int E) {
    int e = blockIdx.x * blockDim.x + threadIdx.x;
    if (e < E) atomicAdd(&deg[__ldg(&dst[e])], 1);
}

__global__ void scan_deg_kernel(const int* __restrict__ deg, int* __restrict__ rowptr,
                                int* __restrict__ cursor, float* __restrict__ invdeg, int n) {
    __shared__ int ssum[1024];
    int tid = threadIdx.x;
    int chunk = (n + 1023) / 1024;
    int lo = tid * chunk;
    int hi = lo + chunk; if (hi > n) hi = n;
    if (lo > n) lo = n;

    int sum = 0;
    for (int i = lo; i < hi; ++i) sum += deg[i];
    ssum[tid] = sum;
    __syncthreads();
    for (int off = 1; off < 1024; off <<= 1) {
        int v = (tid >= off) ? ssum[tid - off] : 0;
        __syncthreads();
        ssum[tid] += v;
        __syncthreads();
    }
    int run = ssum[tid] - sum;  // exclusive prefix
    for (int i = lo; i < hi; ++i) {
        rowptr[i] = run;
        cursor[i] = run;
        float d = (float)deg[i];
        invdeg[i] = 1.0f / fmaxf(d, 1.0f);
        run += deg[i];
    }
    if (tid == 1023) rowptr[n] = ssum[1023];
}

__global__ void fill_csr_kernel(const int* __restrict__ src, const int* __restrict__ dst,
                                int* __restrict__ cursor, int* __restrict__ colidx, int E) {
    int e = blockIdx.x * blockDim.x + threadIdx.x;
    if (e < E) {
        int d = __ldg(&dst[e]);
        int p = atomicAdd(&cursor[d], 1);
        colidx[p] = __ldg(&src[e]);
    }
}

// ------------------- aggregation (mean) with fused epilogue ----------------
// warp per node. Y[i] = act( S[i] + mean_{j in N(i)} P[j] ), P in fp16.
// ACT: 0 = ReLU, 1 = row softmax (D==64 only).

template <int D, int ACT>
__global__ void aggregate_ep(const __half* __restrict__ P, const float* __restrict__ S,
                             const int* __restrict__ rowptr, const int* __restrict__ colidx,
                             const float* __restrict__ invdeg, float* __restrict__ Y, int n) {
    int warp = (blockIdx.x * blockDim.x + threadIdx.x) >> 5;
    int lane = threadIdx.x & 31;
    int nwarps = (gridDim.x * blockDim.x) >> 5;

    for (int i = warp; i < n; i += nwarps) {
        int s = __ldg(&rowptr[i]);
        int e = __ldg(&rowptr[i + 1]);
        float inv = __ldg(&invdeg[i]);

        if (D == 128) {
            float4 acc = make_float4(0.f, 0.f, 0.f, 0.f);
            int j = s;
            for (; j + 3 < e; j += 4) {
                int c0 = __ldg(&colidx[j]);
                int c1 = __ldg(&colidx[j + 1]);
                int c2 = __ldg(&colidx[j + 2]);
                int c3 = __ldg(&colidx[j + 3]);
                uint2 u0 = __ldg((const uint2*)(P + (size_t)c0 * 128) + lane);
                uint2 u1 = __ldg((const uint2*)(P + (size_t)c1 * 128) + lane);
                uint2 u2 = __ldg((const uint2*)(P + (size_t)c2 * 128) + lane);
                uint2 u3 = __ldg((const uint2*)(P + (size_t)c3 * 128) + lane);
                float2 a0 = __half22float2(*(const __half2*)&u0.x);
                float2 b0 = __half22float2(*(const __half2*)&u0.y);
                float2 a1 = __half22float2(*(const __half2*)&u1.x);
                float2 b1 = __half22float2(*(const __half2*)&u1.y);
                float2 a2 = __half22float2(*(const __half2*)&u2.x);
                float2 b2 = __half22float2(*(const __half2*)&u2.y);
                float2 a3 = __half22float2(*(const __half2*)&u3.x);
                float2 b3 = __half22float2(*(const __half2*)&u3.y);
                acc.x += (a0.x + a1.x) + (a2.x + a3.x);
                acc.y += (a0.y + a1.y) + (a2.y + a3.y);
                acc.z += (b0.x + b1.x) + (b2.x + b3.x);
                acc.w += (b0.y + b1.y) + (b2.y + b3.y);
            }
            for (; j < e; ++j) {
                int c0 = __ldg(&colidx[j]);
                uint2 u0 = __ldg((const uint2*)(P + (size_t)c0 * 128) + lane);
                float2 a0 = __half22float2(*(const __half2*)&u0.x);
                float2 b0 = __half22float2(*(const __half2*)&u0.y);
                acc.x += a0.x; acc.y += a0.y; acc.z += b0.x; acc.w += b0.y;
            }
            float4 sv = __ldg((const float4*)(S + (size_t)i * 128) + lane);
            float4 o;
            o.x = fmaxf(fmaf(acc.x, inv, sv.x), 0.f);
            o.y = fmaxf(fmaf(acc.y, inv, sv.y), 0.f);
            o.z = fmaxf(fmaf(acc.z, inv, sv.z), 0.f);
            o.w = fmaxf(fmaf(acc.w, inv, sv.w), 0.f);
            ((float4*)(Y + (size_t)i * 128))[lane] = o;
        } else {  // D == 64
            float2 acc = make_float2(0.f, 0.f);
            int j = s;
            for (; j + 3 < e; j += 4) {
                int c0 = __ldg(&colidx[j]);
                int c1 = __ldg(&colidx[j + 1]);
                int c2 = __ldg(&colidx[j + 2]);
                int c3 = __ldg(&colidx[j + 3]);
                unsigned u0 = __ldg((const unsigned*)(P + (size_t)c0 * 64) + lane);
                unsigned u1 = __ldg((const unsigned*)(P + (size_t)c1 * 64) + lane);
                unsigned u2 = __ldg((const unsigned*)(P + (size_t)c2 * 64) + lane);
                unsigned u3 = __ldg((const unsigned*)(P + (size_t)c3 * 64) + lane);
                float2 f0 = __half22float2(*(const __half2*)&u0);
                float2 f1 = __half22float2(*(const __half2*)&u1);
                float2 f2 = __half22float2(*(const __half2*)&u2);
                float2 f3 = __half22float2(*(const __half2*)&u3);
                acc.x += (f0.x + f1.x) + (f2.x + f3.x);
                acc.y += (f0.y + f1.y) + (f2.y + f3.y);
            }
            for (; j < e; ++j) {
                int c0 = __ldg(&colidx[j]);
                unsigned u0 = __ldg((const unsigned*)(P + (size_t)c0 * 64) + lane);
                float2 f0 = __half22float2(*(const __half2*)&u0);
                acc.x += f0.x; acc.y += f0.y;
            }
            float2 sv = __ldg((const float2*)(S + (size_t)i * 64) + lane);
            float tx = fmaf(acc.x, inv, sv.x);
            float ty = fmaf(acc.y, inv, sv.y);
            if (ACT == 0) {
                ((float2*)(Y + (size_t)i * 64))[lane] = make_float2(fmaxf(tx, 0.f), fmaxf(ty, 0.f));
            } else {
                float m = fmaxf(tx, ty);
#pragma unroll
                for (int o = 16; o; o >>= 1) m = fmaxf(m, __shfl_xor_sync(0xffffffffu, m, o));
                float ex = __expf(tx - m);
                float ey = __expf(ty - m);
                float sm = ex + ey;
#pragma unroll
                for (int o = 16; o; o >>= 1) sm += __shfl_xor_sync(0xffffffffu, sm, o);
                float rinv = 1.0f / sm;
                ((float2*)(Y + (size_t)i * 64))[lane] = make_float2(ex * rinv, ey * rinv);
            }
        }
    }
}

// ----------------------- tensor-core projection GEMM -----------------------
// Per block: C[64 x 128] = A[64 x K] @ Wcat[K, colbase:colbase+128] (+bias on
// S cols). Split-fp16: 3 phases (Ah*Wh, Ah*Wl, Al*Wh) of m16n8k16 MMAs.
// smem: sA [64][2K+8] halves (Ah | Al), sB [2K][136] halves (Wh rows, Wl rows).
// 8 warps = 4 m-strips(16) x 2 n-halves(64). Persistent over row tiles.

template <int K>
__global__ __launch_bounds__(256, 2) void gemm_mma(
    const float* __restrict__ A, const float* __restrict__ Ws,
    const float* __restrict__ Wn, const float* __restrict__ bias,
    float* __restrict__ S, __half* __restrict__ P,
    int n, int HF, int nh) {
    constexpr int LDA = 2 * K + 8;
    constexpr int LDB = 136;
    extern __shared__ __half smh[];
    __half* sA = smh;                 // [64][LDA]
    __half* sB = smh + 64 * LDA;      // [2K][LDB]

    int tid = threadIdx.x;
    int h = blockIdx.x % nh;
    int colbase = h * 128;
    int t0 = blockIdx.x / nh;
    int tstep = gridDim.x / nh;

    // ---- W load + hi/lo split (once per block) ----
    for (int idx = tid; idx < K * 128; idx += 256) {
        int k = idx >> 7, c = idx & 127;
        int gc = colbase + c;
        float w = (gc < HF) ? __ldg(&Ws[k * HF + gc]) : __ldg(&Wn[k * HF + gc - HF]);
        __half wh = __float2half_rn(w);
        __half wl = __float2half_rn(w - __half2float(wh));
        sB[k * LDB + c] = wh;
        sB[(K + k) * LDB + c] = wl;
    }

    int lane = tid & 31;
    int warp = tid >> 5;
    int wm = warp & 3;
    int wn = warp >> 2;

    int arow = wm * 16 + (lane & 15);
    int acolsel = (lane >> 4) * 8;
    int brow = lane & 15;
    int bcol = wn * 64 + (lane >> 4) * 8;

    int ntiles = (n + 63) >> 6;
    for (int t = t0; t < ntiles; t += tstep) {
        int row0g = t * 64;
        __syncthreads();   // sA reuse (and first-iter ordering before A store)
        // ---- A tile load + hi/lo split ----
        for (int idx = tid; idx < 64 * (K / 4); idx += 256) {
            int r  = idx / (K / 4);
            int k4 = idx % (K / 4);
            int gr = row0g + r;
            float4 v = make_float4(0.f, 0.f, 0.f, 0.f);
            if (gr < n) v = __ldg((const float4*)(A + (size_t)gr * K) + k4);
            __half h0 = __float2half_rn(v.x);
            __half h1 = __float2half_rn(v.y);
            __half h2 = __float2half_rn(v.z);
            __half h3 = __float2half_rn(v.w);
            __half l0 = __float2half_rn(v.x - __half2float(h0));
            __half l1 = __float2half_rn(v.y - __half2float(h1));
            __half l2 = __float2half_rn(v.z - __half2float(h2));
            __half l3 = __float2half_rn(v.w - __half2float(h3));
            __half2* ph = (__half2*)&sA[r * LDA + k4 * 4];
            ph[0] = __halves2half2(h0, h1);
            ph[1] = __halves2half2(h2, h3);
            __half2* pl = (__half2*)&sA[r * LDA + K + k4 * 4];
            pl[0] = __halves2half2(l0, l1);
            pl[1] = __halves2half2(l2, l3);
        }
        __syncthreads();

        // ---- init accumulators with bias (S cols only) ----
        float acc[8][4];
#pragma unroll
        for (int nt = 0; nt < 8; ++nt) {
            int gc = colbase + wn * 64 + nt * 8 + (lane & 3) * 2;
            float b0 = 0.f, b1 = 0.f;
            if (gc < HF) { b0 = __ldg(&bias[gc]); b1 = __ldg(&bias[gc + 1]); }
            acc[nt][0] = b0; acc[nt][1] = b1; acc[nt][2] = b0; acc[nt][3] = b1;
        }

        // ---- 3 split phases: (Ah,Wh), (Ah,Wl), (Al,Wh) ----
#pragma unroll
        for (int ph = 0; ph < 3; ++ph) {
            int aOff = (ph == 2) ? K : 0;
            int bOff = (ph == 1) ? K : 0;
#pragma unroll
            for (int k16 = 0; k16 < K; k16 += 16) {
                unsigned a[4];
                unsigned aaddr = su32(&sA[arow * LDA + aOff + k16 + acolsel]);
                LDSM_X4(a, aaddr);
#pragma unroll
                for (int tt = 0; tt < 4; ++tt) {
                    unsigned b[4];
                    unsigned baddr = su32(&sB[(bOff + k16 + brow) * LDB + bcol + tt * 16]);
                    LDSM_X4T(b, baddr);
                    MMA16816(acc[tt * 2],     a, b[0], b[1]);
                    MMA16816(acc[tt * 2 + 1], a, b[2], b[3]);
                }
            }
        }

        // ---- epilogue: S fp32 / P fp16 ----
        int r0 = row0g + wm * 16 + (lane >> 2);
#pragma unroll
        for (int nt = 0; nt < 8; ++nt) {
            int gc = colbase + wn * 64 + nt * 8 + (lane & 3) * 2;
            if (gc < HF) {
                if (r0 < n)
                    *(float2*)(S + (size_t)r0 * HF + gc) = make_float2(acc[nt][0], acc[nt][1]);
                if (r0 + 8 < n)
                    *(float2*)(S + (size_t)(r0 + 8) * HF + gc) = make_float2(acc[nt][2], acc[nt][3]);
            } else {
                int pc = gc - HF;
                if (r0 < n)
                    *(__half2*)(P + (size_t)r0 * HF + pc) = __floats2half2_rn(acc[nt][0], acc[nt][1]);
                if (r0 + 8 < n)
                    *(__half2*)(P + (size_t)(r0 + 8) * HF + pc) = __floats2half2_rn(acc[nt][2], acc[nt][3]);
            }
        }
    }
}

// ---------------------------------------------------------------------------

extern "C" void kernel_launch(void* const* d_in, const int* in_sizes, int n_in,
                              void* d_out, int out_size) {
    const float* x   = (const float*)d_in[0];
    const int*   src = (const int*)d_in[1];
    const int*   dst = (const int*)d_in[2];
    const float* ws1 = (const float*)d_in[3];
    const float* wn1 = (const float*)d_in[4];
    const float* b1  = (const float*)d_in[5];
    const float* ws2 = (const float*)d_in[6];
    const float* wn2 = (const float*)d_in[7];
    const float* b2  = (const float*)d_in[8];
    const float* ws3 = (const float*)d_in[9];
    const float* wn3 = (const float*)d_in[10];
    const float* b3  = (const float*)d_in[11];
    float* out = (float*)d_out;

    int N = in_sizes[0] / 128;
    int E = in_sizes[1];

    int *deg, *rowptr, *cursor, *colidx;
    float *invdeg, *Sb, *hb;
    __half* Pb;
    cudaGetSymbolAddress((void**)&deg,    g_deg);
    cudaGetSymbolAddress((void**)&rowptr, g_rowptr);
    cudaGetSymbolAddress((void**)&cursor, g_cursor);
    cudaGetSymbolAddress((void**)&colidx, g_colidx);
    cudaGetSymbolAddress((void**)&invdeg, g_invdeg);
    cudaGetSymbolAddress((void**)&Sb,     g_S);
    cudaGetSymbolAddress((void**)&Pb,     g_P);
    cudaGetSymbolAddress((void**)&hb,     g_h);

    // dynamic smem: K=128 -> (64*264 + 256*136)*2 = 103424 B; K=64 -> 52224 B
    const int SMEM_K128 = (64 * (2 * 128 + 8) + 2 * 128 * 136) * 2;
    const int SMEM_K64  = (64 * (2 * 64 + 8) + 2 * 64 * 136) * 2;
    cudaFuncSetAttribute((const void*)gemm_mma<128>,
                         cudaFuncAttributeMaxDynamicSharedMemorySize, SMEM_K128);
    cudaFuncSetAttribute((const void*)gemm_mma<64>,
                         cudaFuncAttributeMaxDynamicSharedMemorySize, SMEM_K64);

    // side stream for CSR build, forked/joined via events (capture-safe)
    static cudaStream_t s_csr = 0;
    static cudaEvent_t e_fork = 0, e_join = 0;
    if (!s_csr) {
        cudaStreamCreateWithFlags(&s_csr, cudaStreamNonBlocking);
        cudaEventCreateWithFlags(&e_fork, cudaEventDisableTiming);
        cudaEventCreateWithFlags(&e_join, cudaEventDisableTiming);
    }

    // ---- fork: CSR build on side stream, layer-1 GEMM on main stream ----
    cudaEventRecord(e_fork, 0);
    cudaStreamWaitEvent(s_csr, e_fork, 0);
    zero_int_kernel<<<(N + 255) / 256, 256, 0, s_csr>>>(deg, N);
    count_deg_kernel<<<(E + 255) / 256, 256, 0, s_csr>>>(dst, deg, E);
    scan_deg_kernel<<<1, 1024, 0, s_csr>>>(deg, rowptr, cursor, invdeg, N);
    fill_csr_kernel<<<(E + 255) / 256, 256, 0, s_csr>>>(src, dst, cursor, colidx, E);
    cudaEventRecord(e_join, s_csr);

    // layer-1 GEMM: X(128) -> [S1(128) | P1(128)], 2 col-halves, persistent
    gemm_mma<128><<<296, 256, SMEM_K128>>>(x, ws1, wn1, b1, Sb, Pb, N, 128, 2);
    cudaStreamWaitEvent(0, e_join, 0);   // join before first aggregation

    const int AGG_BLOCKS = 2048;

    // ---- layer 1 ----
    aggregate_ep<128, 0><<<AGG_BLOCKS, 256>>>(Pb, Sb, rowptr, colidx, invdeg, hb, N);
    // ---- layer 2: h1(128) -> [S2(64) | P2(64)] ----
    gemm_mma<128><<<296, 256, SMEM_K128>>>(hb, ws2, wn2, b2, Sb, Pb, N, 64, 1);
    aggregate_ep<64, 0><<<AGG_BLOCKS, 256>>>(Pb, Sb, rowptr, colidx, invdeg, hb, N);
    // ---- layer 3: h2(64) -> [S3(64) | P3(64)] ----
    gemm_mma<64><<<592, 256, SMEM_K64>>>(hb, ws3, wn3, b3, Sb, Pb, N, 64, 1);
    aggregate_ep<64, 1><<<AGG_BLOCKS, 256>>>(Pb, Sb, rowptr, colidx, invdeg, out, N);
}

// round 5
// speedup vs baseline: 1.9305x; 1.1064x over previous
#include <cuda_runtime.h>
#include <cuda_fp16.h>
#include <cuda_bf16.h>
#include <math.h>

// ---------------------------------------------------------------------------
// GraphSAGE (3x SAGEConv mean + ReLU, softmax) on GB300 — round 5.
//  * GEMMs: split-fp16 mma.sync m16n8k16 (Ah*Wh + Ah*Wl + Al*Wh), fp32 accum.
//  * Hidden activations stored PRE-SPLIT (hi|lo fp16) by the aggregation
//    epilogue -> GEMM A-stage is a raw 16B copy (no per-tile conversion).
//  * Single-K-sweep MMA loop (B(hi) fragments reused across 2 phases).
//  * P fp16; CSR (memset+3 kernels) overlapped with layer-1 GEMM.
// ---------------------------------------------------------------------------

#define MAXN 100000
#define MAXE 1600000

__device__ int    g_deg[MAXN];
__device__ int    g_rowptr[MAXN + 1];
__device__ int    g_cursor[MAXN];
__device__ int    g_colidx[MAXE];
__device__ float  g_invdeg[MAXN];
__device__ float  g_S[(size_t)MAXN * 128];       // self-projection (+bias), fp32
__device__ __half g_P[(size_t)MAXN * 128];       // neighbor-projection, fp16
__device__ __half g_hsplit[(size_t)MAXN * 256];  // hidden, (hi|lo) split fp16

static __device__ __forceinline__ unsigned su32(const void* p) {
    return (unsigned)__cvta_generic_to_shared(p);
}

#define LDSM_X4(r, a)                                                          \
    asm volatile("ldmatrix.sync.aligned.m8n8.x4.shared.b16 {%0,%1,%2,%3}, [%4];" \
                 : "=r"((r)[0]), "=r"((r)[1]), "=r"((r)[2]), "=r"((r)[3]) : "r"(a))

#define LDSM_X4T(r, a)                                                         \
    asm volatile("ldmatrix.sync.aligned.m8n8.x4.trans.shared.b16 {%0,%1,%2,%3}, [%4];" \
                 : "=r"((r)[0]), "=r"((r)[1]), "=r"((r)[2]), "=r"((r)[3]) : "r"(a))

#define MMA16816(d, a, b0, b1)                                                 \
    asm volatile("mma.sync.aligned.m16n8k16.row.col.f32.f16.f16.f32 "          \
                 "{%0,%1,%2,%3}, {%4,%5,%6,%7}, {%8,%9}, {%0,%1,%2,%3};"       \
                 : "+f"((d)[0]), "+f"((d)[1]), "+f"((d)[2]), "+f"((d)[3])      \
                 : "r"((a)[0]), "r"((a)[1]), "r"((a)[2]), "r"((a)[3]),         \
                   "r"(b0), "r"(b1))

// ---------------------------- CSR construction ----------------------------

__global__ void count_deg_kernel(const int* __restrict__ dst, int* __restrict__ deg, int E) {
    int e = blockIdx.x * blockDim.x + threadIdx.x;
    if (e < E) atomicAdd(&deg[__ldg(&dst[e])], 1);
}

__global__ void scan_deg_kernel(const int* __restrict__ deg, int* __restrict__ rowptr,
                                int* __restrict__ cursor, float* __restrict__ invdeg, int n) {
    __shared__ int ssum[1024];
    int tid = threadIdx.x;
    int chunk = (n + 1023) / 1024;
    int lo = tid * chunk;
    int hi = lo + chunk; if (hi > n) hi = n;
    if (lo > n) lo = n;

    int sum = 0;
    for (int i = lo; i < hi; ++i) sum += deg[i];
    ssum[tid] = sum;
    __syncthreads();
    for (int off = 1; off < 1024; off <<= 1) {
        int v = (tid >= off) ? ssum[tid - off] : 0;
        __syncthreads();
        ssum[tid] += v;
        __syncthreads();
    }
    int run = ssum[tid] - sum;  // exclusive prefix
    for (int i = lo; i < hi; ++i) {
        rowptr[i] = run;
        cursor[i] = run;
        float d = (float)deg[i];
        invdeg[i] = 1.0f / fmaxf(d, 1.0f);
        run += deg[i];
    }
    if (tid == 1023) rowptr[n] = ssum[1023];
}

__global__ void fill_csr_kernel(const int* __restrict__ src, const int* __restrict__ dst,
                                int* __restrict__ cursor, int* __restrict__ colidx, int E) {
    int e = blockIdx.x * blockDim.x + threadIdx.x;
    if (e < E) {
        int d = __ldg(&dst[e]);
        int p = atomicAdd(&cursor[d], 1);
        colidx[p] = __ldg(&src[e]);
    }
}

// ------------------- aggregation (mean) with fused epilogue ----------------
// warp per node. t = S[i] + mean_{j in N(i)} P[j]  (P fp16, fp32 accumulate)
// ACT 0: Y = relu(t) stored as (hi|lo) fp16 split, row width 2D.
// ACT 1: Y = softmax(t) stored fp32, row width D (D==64 only).

template <int D, int ACT>
__global__ void aggregate_ep(const __half* __restrict__ P, const float* __restrict__ S,
                             const int* __restrict__ rowptr, const int* __restrict__ colidx,
                             const float* __restrict__ invdeg, void* __restrict__ Yv, int n) {
    int warp = (blockIdx.x * blockDim.x + threadIdx.x) >> 5;
    int lane = threadIdx.x & 31;
    int nwarps = (gridDim.x * blockDim.x) >> 5;

    for (int i = warp; i < n; i += nwarps) {
        int s = __ldg(&rowptr[i]);
        int e = __ldg(&rowptr[i + 1]);
        float inv = __ldg(&invdeg[i]);

        if (D == 128) {
            float4 acc = make_float4(0.f, 0.f, 0.f, 0.f);
            int j = s;
            for (; j + 7 < e; j += 8) {
                int c[8];
#pragma unroll
                for (int q = 0; q < 8; ++q) c[q] = __ldg(&colidx[j + q]);
#pragma unroll
                for (int q = 0; q < 8; ++q) {
                    uint2 u = __ldg((const uint2*)(P + (size_t)c[q] * 128) + lane);
                    float2 a = __half22float2(*(const __half2*)&u.x);
                    float2 b = __half22float2(*(const __half2*)&u.y);
                    acc.x += a.x; acc.y += a.y; acc.z += b.x; acc.w += b.y;
                }
            }
            for (; j < e; ++j) {
                int c0 = __ldg(&colidx[j]);
                uint2 u = __ldg((const uint2*)(P + (size_t)c0 * 128) + lane);
                float2 a = __half22float2(*(const __half2*)&u.x);
                float2 b = __half22float2(*(const __half2*)&u.y);
                acc.x += a.x; acc.y += a.y; acc.z += b.x; acc.w += b.y;
            }
            float4 sv = __ldg((const float4*)(S + (size_t)i * 128) + lane);
            float ox = fmaxf(fmaf(acc.x, inv, sv.x), 0.f);
            float oy = fmaxf(fmaf(acc.y, inv, sv.y), 0.f);
            float oz = fmaxf(fmaf(acc.z, inv, sv.z), 0.f);
            float ow = fmaxf(fmaf(acc.w, inv, sv.w), 0.f);
            // split hi/lo and store in gemm layout: [i][0..127]=hi, [128..255]=lo
            __half hx = __float2half_rn(ox), hy = __float2half_rn(oy);
            __half hz = __float2half_rn(oz), hw = __float2half_rn(ow);
            __half lx = __float2half_rn(ox - __half2float(hx));
            __half ly = __float2half_rn(oy - __half2float(hy));
            __half lz = __float2half_rn(oz - __half2float(hz));
            __half lw = __float2half_rn(ow - __half2float(hw));
            __half* Y = (__half*)Yv + (size_t)i * 256;
            __half2 hi01 = __halves2half2(hx, hy), hi23 = __halves2half2(hz, hw);
            __half2 lo01 = __halves2half2(lx, ly), lo23 = __halves2half2(lz, lw);
            *(uint2*)(Y + 4 * lane)       = make_uint2(*(unsigned*)&hi01, *(unsigned*)&hi23);
            *(uint2*)(Y + 128 + 4 * lane) = make_uint2(*(unsigned*)&lo01, *(unsigned*)&lo23);
        } else {  // D == 64
            float2 acc = make_float2(0.f, 0.f);
            int j = s;
            for (; j + 7 < e; j += 8) {
                int c[8];
#pragma unroll
                for (int q = 0; q < 8; ++q) c[q] = __ldg(&colidx[j + q]);
#pragma unroll
                for (int q = 0; q < 8; ++q) {
                    unsigned u = __ldg((const unsigned*)(P + (size_t)c[q] * 64) + lane);
                    float2 f = __half22float2(*(const __half2*)&u);
                    acc.x += f.x; acc.y += f.y;
                }
            }
            for (; j < e; ++j) {
                int c0 = __ldg(&colidx[j]);
                unsigned u = __ldg((const unsigned*)(P + (size_t)c0 * 64) + lane);
                float2 f = __half22float2(*(const __half2*)&u);
                acc.x += f.x; acc.y += f.y;
            }
            float2 sv = __ldg((const float2*)(S + (size_t)i * 64) + lane);
            float tx = fmaf(acc.x, inv, sv.x);
            float ty = fmaf(acc.y, inv, sv.y);
            if (ACT == 0) {
                float ox = fmaxf(tx, 0.f), oy = fmaxf(ty, 0.f);
                __half hx = __float2half_rn(ox), hy = __float2half_rn(oy);
                __half lx = __float2half_rn(ox - __half2float(hx));
                __half ly = __float2half_rn(oy - __half2float(hy));
                __half* Y = (__half*)Yv + (size_t)i * 128;
                __half2 hp = __halves2half2(hx, hy);
                __half2 lp = __halves2half2(lx, ly);
                *(unsigned*)(Y + 2 * lane)      = *(unsigned*)&hp;
                *(unsigned*)(Y + 64 + 2 * lane) = *(unsigned*)&lp;
            } else {
                float m = fmaxf(tx, ty);
#pragma unroll
                for (int o = 16; o; o >>= 1) m = fmaxf(m, __shfl_xor_sync(0xffffffffu, m, o));
                float ex = __expf(tx - m);
                float ey = __expf(ty - m);
                float sm = ex + ey;
#pragma unroll
                for (int o = 16; o; o >>= 1) sm += __shfl_xor_sync(0xffffffffu, sm, o);
                float rinv = 1.0f / sm;
                ((float2*)((float*)Yv + (size_t)i * 64))[lane] = make_float2(ex * rinv, ey * rinv);
            }
        }
    }
}

// ----------------------- tensor-core projection GEMM -----------------------
// Per block: C[64 x 128] = A[64 x K] @ Wcat[K, colbase:colbase+128] (+bias on
// S cols). Split fp16: Ah*Wh + Al*Wh + Ah*Wl, fp32 accumulators.
// PRESPLIT: A is fp16 (hi|lo) row width 2K (raw copy). Else fp32, split here.
// smem: sA [64][2K+8], sB [2K][136]. 8 warps = 4 m-strips x 2 n-halves.

template <int K, bool PRESPLIT>
__global__ __launch_bounds__(256, 2) void gemm_mma(
    const void* __restrict__ Av, const float* __restrict__ Ws,
    const float* __restrict__ Wn, const float* __restrict__ bias,
    float* __restrict__ S, __half* __restrict__ P,
    int n, int HF, int nh) {
    constexpr int LDA = 2 * K + 8;
    constexpr int LDB = 136;
    extern __shared__ __half smh[];
    __half* sA = smh;                 // [64][LDA]
    __half* sB = smh + 64 * LDA;      // [2K][LDB]  (Wh rows 0..K-1, Wl rows K..2K-1)

    int tid = threadIdx.x;
    int h = blockIdx.x % nh;
    int colbase = h * 128;
    int t0 = blockIdx.x / nh;
    int tstep = gridDim.x / nh;

    // ---- W load + hi/lo split (once per block) ----
    for (int idx = tid; idx < K * 128; idx += 256) {
        int k = idx >> 7, c = idx & 127;
        int gc = colbase + c;
        float w = (gc < HF) ? __ldg(&Ws[k * HF + gc]) : __ldg(&Wn[k * HF + gc - HF]);
        __half wh = __float2half_rn(w);
        __half wl = __float2half_rn(w - __half2float(wh));
        sB[k * LDB + c] = wh;
        sB[(K + k) * LDB + c] = wl;
    }

    int lane = tid & 31;
    int warp = tid >> 5;
    int wm = warp & 3;
    int wnh = warp >> 2;

    int arow = wm * 16 + (lane & 15);
    int acolsel = (lane >> 4) * 8;
    int brow = lane & 15;
    int bcol = wnh * 64 + (lane >> 4) * 8;

    // ---- bias init (hoisted out of tile loop) ----
    float2 binit[8];
#pragma unroll
    for (int nt = 0; nt < 8; ++nt) {
        int gc = colbase + wnh * 64 + nt * 8 + (lane & 3) * 2;
        float b0 = 0.f, b1 = 0.f;
        if (gc < HF) { b0 = __ldg(&bias[gc]); b1 = __ldg(&bias[gc + 1]); }
        binit[nt] = make_float2(b0, b1);
    }

    int ntiles = (n + 63) >> 6;
    for (int t = t0; t < ntiles; t += tstep) {
        int row0g = t * 64;
        __syncthreads();   // sA reuse (and first-iter ordering before A store)

        if (PRESPLIT) {
            // raw uint4 copy of pre-split rows (width 2K halves)
            constexpr int CPR = 2 * K / 8;   // uint4 chunks per row
            const __half* A = (const __half*)Av;
            for (int idx = tid; idx < 64 * CPR; idx += 256) {
                int r = idx / CPR, c = idx % CPR;
                int gr = row0g + r;
                uint4 v = make_uint4(0u, 0u, 0u, 0u);
                if (gr < n) v = __ldg((const uint4*)(A + (size_t)gr * 2 * K) + c);
                *(uint4*)&sA[r * LDA + c * 8] = v;
            }
        } else {
            // fp32 A: load + hi/lo split
            const float* A = (const float*)Av;
            for (int idx = tid; idx < 64 * (K / 4); idx += 256) {
                int r  = idx / (K / 4);
                int k4 = idx % (K / 4);
                int gr = row0g + r;
                float4 v = make_float4(0.f, 0.f, 0.f, 0.f);
                if (gr < n) v = __ldg((const float4*)(A + (size_t)gr * K) + k4);
                __half h0 = __float2half_rn(v.x);
                __half h1 = __float2half_rn(v.y);
                __half h2 = __float2half_rn(v.z);
                __half h3 = __float2half_rn(v.w);
                __half l0 = __float2half_rn(v.x - __half2float(h0));
                __half l1 = __float2half_rn(v.y - __half2float(h1));
                __half l2 = __float2half_rn(v.z - __half2float(h2));
                __half l3 = __float2half_rn(v.w - __half2float(h3));
                __half2* ph = (__half2*)&sA[r * LDA + k4 * 4];
                ph[0] = __halves2half2(h0, h1);
                ph[1] = __halves2half2(h2, h3);
                __half2* pl = (__half2*)&sA[r * LDA + K + k4 * 4];
                pl[0] = __halves2half2(l0, l1);
                pl[1] = __halves2half2(l2, l3);
            }
        }
        __syncthreads();

        float acc[8][4];
#pragma unroll
        for (int nt = 0; nt < 8; ++nt) {
            acc[nt][0] = binit[nt].x; acc[nt][1] = binit[nt].y;
            acc[nt][2] = binit[nt].x; acc[nt][3] = binit[nt].y;
        }

        // ---- single K sweep: a_h,a_l loaded once; B(hi) reused 2 phases ----
#pragma unroll
        for (int k16 = 0; k16 < K; k16 += 16) {
            unsigned ah[4], al[4];
            LDSM_X4(ah, su32(&sA[arow * LDA + k16 + acolsel]));
            LDSM_X4(al, su32(&sA[arow * LDA + K + k16 + acolsel]));
#pragma unroll
            for (int tt = 0; tt < 4; ++tt) {
                unsigned bh[4], bl[4];
                LDSM_X4T(bh, su32(&sB[(k16 + brow) * LDB + bcol + tt * 16]));
                MMA16816(acc[tt * 2],     ah, bh[0], bh[1]);
                MMA16816(acc[tt * 2 + 1], ah, bh[2], bh[3]);
                MMA16816(acc[tt * 2],     al, bh[0], bh[1]);
                MMA16816(acc[tt * 2 + 1], al, bh[2], bh[3]);
                LDSM_X4T(bl, su32(&sB[(K + k16 + brow) * LDB + bcol + tt * 16]));
                MMA16816(acc[tt * 2],     ah, bl[0], bl[1]);
                MMA16816(acc[tt * 2 + 1], ah, bl[2], bl[3]);
            }
        }

        // ---- epilogue: S fp32 / P fp16 ----
        int r0 = row0g + wm * 16 + (lane >> 2);
#pragma unroll
        for (int nt = 0; nt < 8; ++nt) {
            int gc = colbase + wnh * 64 + nt * 8 + (lane & 3) * 2;
            if (gc < HF) {
                if (r0 < n)
                    *(float2*)(S + (size_t)r0 * HF + gc) = make_float2(acc[nt][0], acc[nt][1]);
                if (r0 + 8 < n)
                    *(float2*)(S + (size_t)(r0 + 8) * HF + gc) = make_float2(acc[nt][2], acc[nt][3]);
            } else {
                int pc = gc - HF;
                if (r0 < n)
                    *(__half2*)(P + (size_t)r0 * HF + pc) = __floats2half2_rn(acc[nt][0], acc[nt][1]);
                if (r0 + 8 < n)
                    *(__half2*)(P + (size_t)(r0 + 8) * HF + pc) = __floats2half2_rn(acc[nt][2], acc[nt][3]);
            }
        }
    }
}

// ---------------------------------------------------------------------------

extern "C" void kernel_launch(void* const* d_in, const int* in_sizes, int n_in,
                              void* d_out, int out_size) {
    const float* x   = (const float*)d_in[0];
    const int*   src = (const int*)d_in[1];
    const int*   dst = (const int*)d_in[2];
    const float* ws1 = (const float*)d_in[3];
    const float* wn1 = (const float*)d_in[4];
    const float* b1  = (const float*)d_in[5];
    const float* ws2 = (const float*)d_in[6];
    const float* wn2 = (const float*)d_in[7];
    const float* b2  = (const float*)d_in[8];
    const float* ws3 = (const float*)d_in[9];
    const float* wn3 = (const float*)d_in[10];
    const float* b3  = (const float*)d_in[11];
    float* out = (float*)d_out;

    int N = in_sizes[0] / 128;
    int E = in_sizes[1];

    int *deg, *rowptr, *cursor, *colidx;
    float *invdeg, *Sb;
    __half *Pb, *hs;
    cudaGetSymbolAddress((void**)&deg,    g_deg);
    cudaGetSymbolAddress((void**)&rowptr, g_rowptr);
    cudaGetSymbolAddress((void**)&cursor, g_cursor);
    cudaGetSymbolAddress((void**)&colidx, g_colidx);
    cudaGetSymbolAddress((void**)&invdeg, g_invdeg);
    cudaGetSymbolAddress((void**)&Sb,     g_S);
    cudaGetSymbolAddress((void**)&Pb,     g_P);
    cudaGetSymbolAddress((void**)&hs,     g_hsplit);

    const int SMEM_K128 = (64 * (2 * 128 + 8) + 2 * 128 * 136) * 2;  // 103424
    const int SMEM_K64  = (64 * (2 * 64 + 8) + 2 * 64 * 136) * 2;    //  52224
    cudaFuncSetAttribute((const void*)gemm_mma<128, false>,
                         cudaFuncAttributeMaxDynamicSharedMemorySize, SMEM_K128);
    cudaFuncSetAttribute((const void*)gemm_mma<128, true>,
                         cudaFuncAttributeMaxDynamicSharedMemorySize, SMEM_K128);
    cudaFuncSetAttribute((const void*)gemm_mma<64, true>,
                         cudaFuncAttributeMaxDynamicSharedMemorySize, SMEM_K64);

    // side stream for CSR build, forked/joined via events (capture-safe)
    static cudaStream_t s_csr = 0;
    static cudaEvent_t e_fork = 0, e_join = 0;
    if (!s_csr) {
        cudaStreamCreateWithFlags(&s_csr, cudaStreamNonBlocking);
        cudaEventCreateWithFlags(&e_fork, cudaEventDisableTiming);
        cudaEventCreateWithFlags(&e_join, cudaEventDisableTiming);
    }

    // ---- fork: CSR build on side stream, layer-1 GEMM on main stream ----
    cudaEventRecord(e_fork, 0);
    cudaStreamWaitEvent(s_csr, e_fork, 0);
    cudaMemsetAsync(deg, 0, N * sizeof(int), s_csr);
    count_deg_kernel<<<(E + 255) / 256, 256, 0, s_csr>>>(dst, deg, E);
    scan_deg_kernel<<<1, 1024, 0, s_csr>>>(deg, rowptr, cursor, invdeg, N);
    fill_csr_kernel<<<(E + 255) / 256, 256, 0, s_csr>>>(src, dst, cursor, colidx, E);
    cudaEventRecord(e_join, s_csr);

    // layer-1 GEMM: X(128 fp32) -> [S1(128) | P1(128)], 2 col-halves
    gemm_mma<128, false><<<296, 256, SMEM_K128>>>(x, ws1, wn1, b1, Sb, Pb, N, 128, 2);
    cudaStreamWaitEvent(0, e_join, 0);   // join before first aggregation

    const int AGG_BLOCKS = 2048;

    // ---- layer 1: h1split = split(relu(S1 + agg(P1))) ----
    aggregate_ep<128, 0><<<AGG_BLOCKS, 256>>>(Pb, Sb, rowptr, colidx, invdeg, hs, N);
    // ---- layer 2: h1split(K=128) -> [S2(64) | P2(64)] ----
    gemm_mma<128, true><<<296, 256, SMEM_K128>>>(hs, ws2, wn2, b2, Sb, Pb, N, 64, 1);
    aggregate_ep<64, 0><<<AGG_BLOCKS, 256>>>(Pb, Sb, rowptr, colidx, invdeg, hs, N);
    // ---- layer 3: h2split(K=64) -> [S3(64) | P3(64)] ----
    gemm_mma<64, true><<<592, 256, SMEM_K64>>>(hs, ws3, wn3, b3, Sb, Pb, N, 64, 1);
    aggregate_ep<64, 1><<<AGG_BLOCKS, 256>>>(Pb, Sb, rowptr, colidx, invdeg, out, N);
}